// round 6
// baseline (speedup 1.0000x reference)
#include <cuda_runtime.h>
#include <cstdint>

// Problem constants (fixed by reference setup_inputs)
#define B_SZ   16
#define T_IN   512
#define D_DIM  768
#define D4     (D_DIM / 4)       // 192 float4 per row = blockDim
#define PH     4                 // phonemes per block
#define NBLK   (T_IN / PH)       // 128 blocks per batch
#define ROW_BYTES (D_DIM * 4)    // 3072 bytes per frame row

// Fused: redundant per-block duration reduce + TMA bulk-copy scatter.
// durations are int32 on device (JAX default config downgrades int64).
__global__ void __launch_bounds__(D4) lr_tma_kernel(
    const float4* __restrict__ hidden,
    const int*    __restrict__ durations,
    float4*       __restrict__ out,
    int t_out) {
    __shared__ float4 srow[PH * D4];         // 12KB: staged source rows
    __shared__ int    sdur[T_IN];
    __shared__ int    red_b[6], red_a[6];

    const int blk  = blockIdx.x;             // 0..NBLK-1
    const int b    = blockIdx.y;
    const int i0   = blk * PH;
    const int tid  = threadIdx.x;            // 0..191
    const int lane = tid & 31;
    const int wid  = tid >> 5;               // 0..5

    // ---- Phase 0: row loads (depend only on blockIdx -> issue immediately) ----
    float4 v[PH];
    #pragma unroll
    for (int k = 0; k < PH; ++k)
        v[k] = __ldg(hidden + ((size_t)b * T_IN + i0 + k) * D4 + tid);

    // ---- Phase 1: durations -> prefix-before-i0 and total (redundant per block) ----
    const int* durb = durations + b * T_IN;
    int before = 0, all = 0;
    #pragma unroll
    for (int j = tid; j < T_IN; j += D4) {   // 3 strided iterations
        int dv = __ldg(durb + j);
        sdur[j] = dv;
        all += dv;
        if (j < i0) before += dv;
    }
    #pragma unroll
    for (int off = 16; off > 0; off >>= 1) {
        before += __shfl_down_sync(0xFFFFFFFFu, before, off);
        all    += __shfl_down_sync(0xFFFFFFFFu, all, off);
    }
    if (lane == 0) { red_b[wid] = before; red_a[wid] = all; }

    // ---- Phase 2: stage rows into SMEM for the TMA engine ----
    #pragma unroll
    for (int k = 0; k < PH; ++k)
        srow[k * D4 + tid] = v[k];

    // Generic-proxy writes must be visible to the async proxy before TMA reads.
    asm volatile("fence.proxy.async.shared::cta;" ::: "memory");
    __syncthreads();

    int base = 0, total = 0;
    #pragma unroll
    for (int w = 0; w < 6; ++w) { base += red_b[w]; total += red_a[w]; }

    float4* const out_b = out + (size_t)b * t_out * D4;

    // ---- Phase 3: thread 0 issues one bulk copy per output frame ----
    if (tid == 0) {
        const uint32_t s0 = (uint32_t)__cvta_generic_to_shared(srow);
        int run = base;
        #pragma unroll
        for (int k = 0; k < PH; ++k) {
            const int dur = sdur[i0 + k];
            const uint32_t src = s0 + k * ROW_BYTES;
            char* dst = (char*)out_b + (size_t)run * ROW_BYTES;
            for (int j = 0; j < dur; ++j) {
                asm volatile(
                    "cp.async.bulk.global.shared::cta.bulk_group [%0], [%1], %2;"
                    :: "l"(dst + (size_t)j * ROW_BYTES), "r"(src), "r"(ROW_BYTES)
                    : "memory");
            }
            run += dur;
        }
        asm volatile("cp.async.bulk.commit_group;" ::: "memory");
    }

    // ---- Phase 4: padding frames [total, t_out) with plain stores (small) ----
    const float4 z = make_float4(0.f, 0.f, 0.f, 0.f);
    for (int t = total + blk; t < t_out; t += NBLK)
        out_b[(size_t)t * D4 + tid] = z;

    // Block must not exit (SMEM reuse) until TMA has finished READING srow.
    // GMEM writes may still be draining after exit - that is safe.
    if (tid == 0)
        asm volatile("cp.async.bulk.wait_group.read 0;" ::: "memory");
}

extern "C" void kernel_launch(void* const* d_in, const int* in_sizes, int n_in,
                              void* d_out, int out_size) {
    const float* hidden    = (const float*)d_in[0];  // (B, T_IN, D) f32
    const int*   durations = (const int*)d_in[1];    // (B, T_IN) int32

    const int t_out = out_size / (B_SZ * D_DIM);

    dim3 grid(NBLK, B_SZ);
    lr_tma_kernel<<<grid, D4>>>((const float4*)hidden, durations,
                                (float4*)d_out, t_out);
}